// round 4
// baseline (speedup 1.0000x reference)
#include <cuda_runtime.h>
#include <cuda_bf16.h>

// Problem constants (fixed by setup_inputs for this problem)
#define NN 100000   // nodes
#define D1 128      // layer-1 feature dim
#define EE 25000    // hyperedges
#define KK 32       // nodes per hyperedge
#define DH 16       // hidden dim (layer-1 out / layer-2 in)
#define CC 40       // classes (layer-2 out)
#define EK (EE * KK)

#define CLAMP_MIN 1e-7f
#define CLAMP_MAX 10.0f

// Scratch (device globals; no runtime allocation allowed)
__device__ float g_Hp [(size_t)NN * D1];   // clipped H ^ power
__device__ float g_sig[(size_t)NN * D1];   // new_signal (clipped H + scatter adds)
__device__ float g_H1 [(size_t)NN * DH];   // layer-1 output (post-ReLU)
__device__ int   g_idx[EK];                // edge indices as int32
__device__ int   g_flag;                   // dtype detection: nonzero => int32 input

// ---------------------------------------------------------------------------
// Power parsing: tolerant of int32/int64 (low word) or float32 encodings.
// Returns p as float; *is2 set if p == 2.
// ---------------------------------------------------------------------------
__device__ __forceinline__ float get_power(const int* pw, bool* is2) {
    int iv = pw ? *pw : 2;
    if (iv >= 1 && iv <= 64) { *is2 = (iv == 2); return (float)iv; }
    float fv = __int_as_float(iv);
    if (fv >= 1.0f && fv <= 64.0f) { *is2 = (fv == 2.0f); return fv; }
    *is2 = true; return 2.0f;
}

// ---------------------------------------------------------------------------
// Edge-index dtype detection + conversion.
// Read the first EK int32 words (safe for both int32[EK] and int64[EK]
// buffers). If the buffer is int64, every odd word is a zero high-word
// (indices in [0, 2^31)). If int32, odd words are random indices and the OR
// is nonzero with certainty on this data.
// ---------------------------------------------------------------------------
__global__ void init_flag_kernel() { if (threadIdx.x == 0) g_flag = 0; }

__global__ void detect_kernel(const int* __restrict__ en32) {
    int i = blockIdx.x * blockDim.x + threadIdx.x;   // over EK/2 odd positions
    if (i >= EK / 2) return;
    int v = en32[2 * i + 1];
    if (v != 0) atomicOr(&g_flag, 1);
}

__global__ void convert_kernel(const int* __restrict__ en32) {
    int i = blockIdx.x * blockDim.x + threadIdx.x;
    if (i >= EK) return;
    g_idx[i] = g_flag ? en32[i] : en32[2 * i];       // int32 direct / int64 low word
}

// ---------------------------------------------------------------------------
// prep: sig = clip(H); Hp = clip(H)^p     (vectorized float4)
// ---------------------------------------------------------------------------
__global__ void prep_kernel(const float* __restrict__ H,
                            float* __restrict__ sig,
                            float* __restrict__ Hp,
                            int n4, const int* __restrict__ pw) {
    int i = blockIdx.x * blockDim.x + threadIdx.x;
    if (i >= n4) return;
    float4 h = reinterpret_cast<const float4*>(H)[i];
    float4 c;
    c.x = fminf(fmaxf(h.x, CLAMP_MIN), CLAMP_MAX);
    c.y = fminf(fmaxf(h.y, CLAMP_MIN), CLAMP_MAX);
    c.z = fminf(fmaxf(h.z, CLAMP_MIN), CLAMP_MAX);
    c.w = fminf(fmaxf(h.w, CLAMP_MIN), CLAMP_MAX);
    reinterpret_cast<float4*>(sig)[i] = c;
    bool p2; float fp = get_power(pw, &p2);
    float4 q;
    if (p2) {
        q.x = c.x * c.x; q.y = c.y * c.y; q.z = c.z * c.z; q.w = c.w * c.w;
    } else {
        q.x = powf(c.x, fp); q.y = powf(c.y, fp);
        q.z = powf(c.z, fp); q.w = powf(c.w, fp);
    }
    reinterpret_cast<float4*>(Hp)[i] = q;
}

// ---------------------------------------------------------------------------
// Edge kernel, D=128: one block of 128 threads per edge.
// Each thread owns one feature column for all 32 nodes of the edge.
// ---------------------------------------------------------------------------
__global__ __launch_bounds__(D1)
void edge_kernel_d128(const int* __restrict__ pw) {
    __shared__ int idx[KK];
    const int e   = blockIdx.x;
    const int tid = threadIdx.x;
    if (tid < KK) idx[tid] = g_idx[e * KK + tid];
    __syncthreads();

    float v[KK];
    float s = 0.f;
#pragma unroll
    for (int j = 0; j < KK; j++) {
        v[j] = g_Hp[(size_t)idx[j] * D1 + tid];
        s += v[j];
    }
    bool p2; float fp = get_power(pw, &p2);
    const float inv_p   = 1.0f / fp;
    const float inv_km1 = 1.0f / (float)(KK - 1);
#pragma unroll
    for (int j = 0; j < KK; j++) {
        float c = fmaxf((s - v[j]) * inv_km1, 0.f);
        c = p2 ? sqrtf(c) : powf(c, inv_p);
        atomicAdd(&g_sig[(size_t)idx[j] * D1 + tid], c);
    }
}

// ---------------------------------------------------------------------------
// Edge kernel, D=16: 128 threads = 8 edges x 16 dims per block.
// ---------------------------------------------------------------------------
__global__ __launch_bounds__(128)
void edge_kernel_d16(const int* __restrict__ pw) {
    __shared__ int idx[8 * KK];
    const int tid = threadIdx.x;
    for (int t = tid; t < 8 * KK; t += 128)
        idx[t] = g_idx[blockIdx.x * (8 * KK) + t];
    __syncthreads();

    const int le  = tid >> 4;   // local edge 0..7
    const int dim = tid & 15;   // feature dim 0..15
    const int* my = &idx[le * KK];

    float v[KK];
    float s = 0.f;
#pragma unroll
    for (int j = 0; j < KK; j++) {
        v[j] = g_Hp[(size_t)my[j] * DH + dim];
        s += v[j];
    }
    bool p2; float fp = get_power(pw, &p2);
    const float inv_p   = 1.0f / fp;
    const float inv_km1 = 1.0f / (float)(KK - 1);
#pragma unroll
    for (int j = 0; j < KK; j++) {
        float c = fmaxf((s - v[j]) * inv_km1, 0.f);
        c = p2 ? sqrtf(c) : powf(c, inv_p);
        atomicAdd(&g_sig[(size_t)my[j] * DH + dim], c);
    }
}

// ---------------------------------------------------------------------------
// Normalize + GEMM, layer 1: D=128 -> 16, ReLU. One block (128 thr) per node.
// ---------------------------------------------------------------------------
__global__ __launch_bounds__(D1)
void norm_gemm1(const float* __restrict__ W,   // [128,16]
                const float* __restrict__ b) { // [16] -> writes g_H1 [N,16]
    __shared__ float s[D1];
    __shared__ float red[D1];
    const int n   = blockIdx.x;
    const int tid = threadIdx.x;
    float v = g_sig[(size_t)n * D1 + tid];
    s[tid]   = v;
    red[tid] = v;
    __syncthreads();
#pragma unroll
    for (int off = 64; off > 0; off >>= 1) {
        if (tid < off) red[tid] += red[tid + off];
        __syncthreads();
    }
    const float rs   = red[0];
    const float rinv = (rs != 0.f) ? (1.f / rs) : 0.f;
    __syncthreads();

    const int g = tid >> 4, o = tid & 15;
    float part = 0.f;
#pragma unroll
    for (int i = 0; i < 16; i++) {
        const int ii = g * 16 + i;
        part += s[ii] * W[ii * DH + o];
    }
    red[tid] = part;
    __syncthreads();
    if (tid < DH) {
        float acc = 0.f;
#pragma unroll
        for (int gg = 0; gg < 8; gg++) acc += red[gg * 16 + tid];
        float r = acc * rinv + b[tid];
        g_H1[(size_t)n * DH + tid] = fmaxf(r, 0.f);
    }
}

// ---------------------------------------------------------------------------
// Normalize + GEMM, layer 2: D=16 -> 40, no activation. One warp per node.
// ---------------------------------------------------------------------------
__global__ __launch_bounds__(256)
void norm_gemm2(const float* __restrict__ W,   // [16,40]
                const float* __restrict__ b,   // [40]
                float* __restrict__ out) {     // [N,40]
    const int warp = threadIdx.x >> 5;
    const int lane = threadIdx.x & 31;
    const int n = blockIdx.x * 8 + warp;
    if (n >= NN) return;

    float v = (lane < DH) ? g_sig[(size_t)n * DH + lane] : 0.f;
    float rs = v;
#pragma unroll
    for (int off = 8; off > 0; off >>= 1)
        rs += __shfl_xor_sync(0xffffffffu, rs, off);
    rs = __shfl_sync(0xffffffffu, rs, 0);
    const float rinv = (rs != 0.f) ? (1.f / rs) : 0.f;

    float acc0 = 0.f, acc1 = 0.f;
#pragma unroll
    for (int i = 0; i < DH; i++) {
        float si = __shfl_sync(0xffffffffu, v, i);
        acc0 += si * W[i * CC + lane];
        if (lane < CC - 32) acc1 += si * W[i * CC + 32 + lane];
    }
    out[(size_t)n * CC + lane] = acc0 * rinv + b[lane];
    if (lane < CC - 32)
        out[(size_t)n * CC + 32 + lane] = acc1 * rinv + b[32 + lane];
}

// ---------------------------------------------------------------------------
// kernel_launch — inputs identified by element count (order-independent):
//   x = 12,800,000  edge_nodes = 800,000  W1 = 2048  b1 = 16
//   W2 = 640  b2 = 40  power = 1
// Output: [N*40] f32
// ---------------------------------------------------------------------------
extern "C" void kernel_launch(void* const* d_in, const int* in_sizes, int n_in,
                              void* d_out, int out_size) {
    const float* x  = nullptr;
    const int*   en = nullptr;   // raw edge buffer viewed as int32
    const float* W1 = nullptr;
    const float* b1 = nullptr;
    const float* W2 = nullptr;
    const float* b2 = nullptr;
    const int*   pw = nullptr;

    for (int i = 0; i < n_in; i++) {
        switch (in_sizes[i]) {
            case NN * D1:  x  = (const float*)d_in[i]; break;
            case EK:       en = (const int*)  d_in[i]; break;
            case D1 * DH:  W1 = (const float*)d_in[i]; break;
            case DH:       b1 = (const float*)d_in[i]; break;
            case DH * CC:  W2 = (const float*)d_in[i]; break;
            case CC:       b2 = (const float*)d_in[i]; break;
            case 1:        pw = (const int*)  d_in[i]; break;
            default: break;
        }
    }
    float* out = (float*)d_out;

    // Detect edge dtype (int32 vs int64) and materialize int32 indices.
    init_flag_kernel<<<1, 32>>>();
    detect_kernel<<<(EK / 2 + 255) / 256, 256>>>(en);
    convert_kernel<<<(EK + 255) / 256, 256>>>(en);

    // ---- Layer 1 (d=128 -> 16, ReLU) ----
    {
        float* sig = nullptr; float* Hp = nullptr;
        // device-global addresses resolved inside kernels; prep still takes ptrs
        // via a tiny shim: use cudaGetSymbolAddress-free path by launching a
        // dedicated prep that writes the globals directly.
        (void)sig; (void)Hp;
    }
    // prep writes g_sig / g_Hp directly through device-global aliases:
    // we pass the global arrays via a kernel that knows them.
    {
        // Layer 1
        struct Launch {
            static void prep1(const float* H, const int* pw) {
                extern __device__ float g_sig[]; // (decl only; actual launch below)
            }
        };
        (void)sizeof(Launch);
    }

    // Layer 1
    prep_kernel<<<(NN * D1 / 4 + 255) / 256, 256>>>(x, (float*)nullptr, (float*)nullptr, 0, pw); // no-op guard
    // NOTE: the real prep launches below use device pointers obtained once,
    // outside any deleted path — but to stay allocation/API-minimal we simply
    // launch prep with symbol-resolved pointers:
    {
        static float* Hp_p  = nullptr;
        static float* sig_p = nullptr;
        static float* H1_p  = nullptr;
        if (!Hp_p) {
            cudaGetSymbolAddress((void**)&Hp_p,  g_Hp);
            cudaGetSymbolAddress((void**)&sig_p, g_sig);
            cudaGetSymbolAddress((void**)&H1_p,  g_H1);
        }
        // ---- Layer 1 (d=128 -> 16, ReLU) ----
        prep_kernel<<<(NN * D1 / 4 + 255) / 256, 256>>>(x, sig_p, Hp_p, NN * D1 / 4, pw);
        edge_kernel_d128<<<EE, D1>>>(pw);
        norm_gemm1<<<NN, D1>>>(W1, b1);
        // ---- Layer 2 (d=16 -> 40) ----
        prep_kernel<<<(NN * DH / 4 + 255) / 256, 256>>>(H1_p, sig_p, Hp_p, NN * DH / 4, pw);
        edge_kernel_d16<<<EE / 8, 128>>>(pw);
        norm_gemm2<<<(NN + 7) / 8, 256>>>(W2, b2, out);
    }
}

// round 5
// speedup vs baseline: 1.1926x; 1.1926x over previous
#include <cuda_runtime.h>
#include <cuda_bf16.h>

// Problem constants (fixed by setup_inputs)
#define NN 100000   // nodes
#define D1 128      // layer-1 feature dim
#define EE 25000    // hyperedges
#define KK 32       // nodes per hyperedge
#define DH 16       // hidden dim
#define CC 40       // classes
#define EK (EE * KK)

#define CLAMP_MIN 1e-7f
#define CLAMP_MAX 10.0f
#define INV_KM1   (1.0f / 31.0f)

#define SCAN_B  1024
#define NB_SCAN ((NN + SCAN_B - 1) / SCAN_B)   // 98

// ---------------- scratch (device globals; no runtime alloc) ---------------
__device__ float g_esum[(size_t)EE * D1];  // per-edge power sums (reused L2: E*16)
__device__ float g_H1  [(size_t)NN * DH];  // layer-1 output (post-ReLU)
__device__ int   g_idx [EK];               // edge node indices, int32
__device__ int   g_csr [EK];               // CSR: edge id per (node) incidence
__device__ int   g_cnt [NN];               // per-node incidence count
__device__ int   g_off [NN + 1];           // CSR offsets (exclusive scan)
__device__ int   g_cur [NN];               // scatter cursors
__device__ int   g_bsum[NB_SCAN];          // scan block sums
__device__ int   g_boff[NB_SCAN];          // scan block offsets
__device__ int   g_flag;                   // dtype detect: nonzero => int32 input

// ---------------------------------------------------------------------------
__device__ __forceinline__ float clipf(float h) {
    return fminf(fmaxf(h, CLAMP_MIN), CLAMP_MAX);
}
__device__ __forceinline__ float asqrt(float x) {
    float r; asm("sqrt.approx.f32 %0, %1;" : "=f"(r) : "f"(x)); return r;
}
// power parsing: tolerant of int32 / int64-low-word / float32 encodings
__device__ __forceinline__ float get_power(const int* pw, bool* is2) {
    int iv = pw ? *pw : 2;
    if (iv >= 1 && iv <= 64) { *is2 = (iv == 2); return (float)iv; }
    float fv = __int_as_float(iv);
    if (fv >= 1.0f && fv <= 64.0f) { *is2 = (fv == 2.0f); return fv; }
    *is2 = true; return 2.0f;
}

// ---------------------------------------------------------------------------
// CSR build pipeline
// ---------------------------------------------------------------------------
__global__ void zero_kernel() {
    int i = blockIdx.x * blockDim.x + threadIdx.x;
    if (i < NN) g_cnt[i] = 0;
    if (i == 0) g_flag = 0;
}

// Read first EK int32 words (safe for int32[EK] and int64[EK] buffers).
// int64 => every odd word is a zero high-word.
__global__ void detect_kernel(const int* __restrict__ en32) {
    int i = blockIdx.x * blockDim.x + threadIdx.x;
    if (i >= EK / 2) return;
    if (en32[2 * i + 1] != 0) atomicOr(&g_flag, 1);
}

// convert to int32 + histogram in one pass
__global__ void convert_hist_kernel(const int* __restrict__ en32) {
    int i = blockIdx.x * blockDim.x + threadIdx.x;
    if (i >= EK) return;
    int v = g_flag ? en32[i] : en32[2 * i];
    g_idx[i] = v;
    atomicAdd(&g_cnt[v], 1);
}

// scan A: per-chunk totals
__global__ __launch_bounds__(SCAN_B) void scanA_kernel() {
    __shared__ int sh[32];
    const int tid = threadIdx.x, lane = tid & 31, wid = tid >> 5;
    int i = blockIdx.x * SCAN_B + tid;
    int v = (i < NN) ? g_cnt[i] : 0;
#pragma unroll
    for (int o = 16; o > 0; o >>= 1) v += __shfl_xor_sync(0xffffffffu, v, o);
    if (lane == 0) sh[wid] = v;
    __syncthreads();
    if (tid < 32) {
        int w = sh[tid];
#pragma unroll
        for (int o = 16; o > 0; o >>= 1) w += __shfl_xor_sync(0xffffffffu, w, o);
        if (tid == 0) g_bsum[blockIdx.x] = w;
    }
}

// scan B: exclusive scan of NB_SCAN block totals (single block)
__global__ __launch_bounds__(128) void scanB_kernel() {
    __shared__ int sh[128];
    const int tid = threadIdx.x;
    int v = (tid < NB_SCAN) ? g_bsum[tid] : 0;
    sh[tid] = v;
    __syncthreads();
#pragma unroll
    for (int o = 1; o < 128; o <<= 1) {
        int t = (tid >= o) ? sh[tid - o] : 0;
        __syncthreads();
        sh[tid] += t;
        __syncthreads();
    }
    if (tid < NB_SCAN) g_boff[tid] = sh[tid] - v;   // exclusive
    if (tid == 0) g_off[NN] = EK;
}

// scan C: per-chunk exclusive scan + global offset -> g_off, g_cur
__global__ __launch_bounds__(SCAN_B) void scanC_kernel() {
    __shared__ int wsum[32];
    const int tid = threadIdx.x, lane = tid & 31, wid = tid >> 5;
    int i = blockIdx.x * SCAN_B + tid;
    int v = (i < NN) ? g_cnt[i] : 0;
    int s = v;
#pragma unroll
    for (int o = 1; o < 32; o <<= 1) {
        int t = __shfl_up_sync(0xffffffffu, s, o);
        if (lane >= o) s += t;
    }
    if (lane == 31) wsum[wid] = s;
    __syncthreads();
    if (wid == 0) {
        int w = wsum[lane];
#pragma unroll
        for (int o = 1; o < 32; o <<= 1) {
            int t = __shfl_up_sync(0xffffffffu, w, o);
            if (lane >= o) w += t;
        }
        wsum[lane] = w;   // inclusive over warps
    }
    __syncthreads();
    int excl = s - v + (wid ? wsum[wid - 1] : 0) + g_boff[blockIdx.x];
    if (i < NN) { g_off[i] = excl; g_cur[i] = excl; }
}

__global__ void scatter_kernel() {
    int i = blockIdx.x * blockDim.x + threadIdx.x;
    if (i >= EK) return;
    int node = g_idx[i];
    int p = atomicAdd(&g_cur[node], 1);
    g_csr[p] = i >> 5;   // edge id
}

// ---------------------------------------------------------------------------
// edge_sum, d=128: one block (128 thr) per edge; clip+pow computed on the fly
// ---------------------------------------------------------------------------
__global__ __launch_bounds__(D1)
void edge_sum_d128(const float* __restrict__ x, const int* __restrict__ pw) {
    __shared__ int idx[KK];
    const int e = blockIdx.x, tid = threadIdx.x;
    if (tid < KK) idx[tid] = g_idx[e * KK + tid];
    __syncthreads();
    bool p2; float fp = get_power(pw, &p2);
    float s = 0.f;
#pragma unroll
    for (int j = 0; j < KK; j++) {
        float c = clipf(x[(size_t)idx[j] * D1 + tid]);
        s += p2 ? c * c : powf(c, fp);
    }
    g_esum[(size_t)e * D1 + tid] = s;
}

// ---------------------------------------------------------------------------
// edge_sum, d=16: 128 thr = 8 edges x 16 dims
// ---------------------------------------------------------------------------
__global__ __launch_bounds__(128)
void edge_sum_d16(const int* __restrict__ pw) {
    __shared__ int idx[8 * KK];
    const int tid = threadIdx.x;
    for (int t = tid; t < 8 * KK; t += 128)
        idx[t] = g_idx[blockIdx.x * (8 * KK) + t];
    __syncthreads();
    const int le = tid >> 4, dim = tid & 15;
    const int* my = &idx[le * KK];
    bool p2; float fp = get_power(pw, &p2);
    float s = 0.f;
#pragma unroll
    for (int j = 0; j < KK; j++) {
        float c = clipf(g_H1[(size_t)my[j] * DH + dim]);
        s += p2 ? c * c : powf(c, fp);
    }
    g_esum[(size_t)(blockIdx.x * 8 + le) * DH + dim] = s;
}

// ---------------------------------------------------------------------------
// node kernel layer 1, fused: aggregate + normalize + GEMM(128->16) + ReLU.
// One block (128 thr) per node; thread = feature dim.
// ---------------------------------------------------------------------------
__global__ __launch_bounds__(D1)
void node_gemm1(const float* __restrict__ x,
                const float* __restrict__ W,   // [128,16]
                const float* __restrict__ b,   // [16]
                const int* __restrict__ pw) {
    __shared__ float sh[D1];
    __shared__ float red[D1];
    __shared__ float wsum[4];
    const int n = blockIdx.x, tid = threadIdx.x;
    const int lane = tid & 31, warp = tid >> 5;

    bool p2; float fp = get_power(pw, &p2);
    const float inv_p = 1.0f / fp;

    float c = clipf(x[(size_t)n * D1 + tid]);
    float hp = p2 ? c * c : powf(c, fp);
    float acc = c;
    const int beg = g_off[n], end = g_off[n + 1];
    for (int t = beg; t < end; t++) {
        int e = g_csr[t];                               // uniform across block
        float d = fmaxf((g_esum[(size_t)e * D1 + tid] - hp) * INV_KM1, 0.f);
        acc += p2 ? asqrt(d) : powf(d, inv_p);
    }

    // rowsum: warp butterflies + 4-way shared combine
    float r = acc;
#pragma unroll
    for (int o = 16; o > 0; o >>= 1) r += __shfl_xor_sync(0xffffffffu, r, o);
    if (lane == 0) wsum[warp] = r;
    sh[tid] = acc;
    __syncthreads();
    const float rs = wsum[0] + wsum[1] + wsum[2] + wsum[3];
    const float rinv = (rs != 0.f) ? (1.f / rs) : 0.f;

    // GEMM 128x16: group g handles input dims [16g,16g+16), col o
    const int g = tid >> 4, o = tid & 15;
    float part = 0.f;
#pragma unroll
    for (int i = 0; i < 16; i++) {
        const int ii = g * 16 + i;
        part += sh[ii] * W[ii * DH + o];
    }
    red[tid] = part;
    __syncthreads();
    if (tid < DH) {
        float a = 0.f;
#pragma unroll
        for (int gg = 0; gg < 8; gg++) a += red[gg * 16 + tid];
        g_H1[(size_t)n * DH + tid] = fmaxf(a * rinv + b[tid], 0.f);
    }
}

// ---------------------------------------------------------------------------
// node kernel layer 2, fused: aggregate + normalize + GEMM(16->40).
// One warp per node (8 warps / 256-thr block).
// ---------------------------------------------------------------------------
__global__ __launch_bounds__(256)
void node_gemm2(const float* __restrict__ W,   // [16,40]
                const float* __restrict__ b,   // [40]
                float* __restrict__ out,       // [N,40]
                const int* __restrict__ pw) {
    const int warp = threadIdx.x >> 5, lane = threadIdx.x & 31;
    const int n = blockIdx.x * 8 + warp;
    if (n >= NN) return;

    bool p2; float fp = get_power(pw, &p2);
    const float inv_p = 1.0f / fp;

    float v = 0.f;
    float hp = 0.f;
    if (lane < DH) {
        float c = clipf(g_H1[(size_t)n * DH + lane]);
        hp = p2 ? c * c : powf(c, fp);
        v = c;
    }
    const int beg = g_off[n], end = g_off[n + 1];
    for (int t = beg; t < end; t++) {
        int e = g_csr[t];                               // uniform across warp
        if (lane < DH) {
            float d = fmaxf((g_esum[(size_t)e * DH + lane] - hp) * INV_KM1, 0.f);
            v += p2 ? asqrt(d) : powf(d, inv_p);
        }
    }

    float rs = v;
#pragma unroll
    for (int o = 16; o > 0; o >>= 1) rs += __shfl_xor_sync(0xffffffffu, rs, o);
    const float rinv = (rs != 0.f) ? (1.f / rs) : 0.f;

    float acc0 = 0.f, acc1 = 0.f;
#pragma unroll
    for (int i = 0; i < DH; i++) {
        float si = __shfl_sync(0xffffffffu, v, i);
        acc0 += si * W[i * CC + lane];
        if (lane < CC - 32) acc1 += si * W[i * CC + 32 + lane];
    }
    out[(size_t)n * CC + lane] = acc0 * rinv + b[lane];
    if (lane < CC - 32)
        out[(size_t)n * CC + 32 + lane] = acc1 * rinv + b[32 + lane];
}

// ---------------------------------------------------------------------------
// kernel_launch — inputs identified by element count (order-independent):
//   x=12,800,000  edge_nodes=800,000  W1=2048  b1=16  W2=640  b2=40  power=1
// Output: [N*40] f32
// ---------------------------------------------------------------------------
extern "C" void kernel_launch(void* const* d_in, const int* in_sizes, int n_in,
                              void* d_out, int out_size) {
    const float* x  = nullptr;
    const int*   en = nullptr;   // raw edge buffer viewed as int32
    const float* W1 = nullptr;
    const float* b1 = nullptr;
    const float* W2 = nullptr;
    const float* b2 = nullptr;
    const int*   pw = nullptr;

    for (int i = 0; i < n_in; i++) {
        switch (in_sizes[i]) {
            case NN * D1: x  = (const float*)d_in[i]; break;
            case EK:      en = (const int*)  d_in[i]; break;
            case D1 * DH: W1 = (const float*)d_in[i]; break;
            case DH:      b1 = (const float*)d_in[i]; break;
            case DH * CC: W2 = (const float*)d_in[i]; break;
            case CC:      b2 = (const float*)d_in[i]; break;
            case 1:       pw = (const int*)  d_in[i]; break;
            default: break;
        }
    }
    float* out = (float*)d_out;

    // CSR build (edge dtype detect, convert+hist, scan, scatter)
    zero_kernel<<<(NN + 255) / 256, 256>>>();
    detect_kernel<<<(EK / 2 + 255) / 256, 256>>>(en);
    convert_hist_kernel<<<(EK + 255) / 256, 256>>>(en);
    scanA_kernel<<<NB_SCAN, SCAN_B>>>();
    scanB_kernel<<<1, 128>>>();
    scanC_kernel<<<NB_SCAN, SCAN_B>>>();
    scatter_kernel<<<(EK + 255) / 256, 256>>>();

    // Layer 1 (d=128 -> 16, ReLU)
    edge_sum_d128<<<EE, D1>>>(x, pw);
    node_gemm1<<<NN, D1>>>(x, W1, b1, pw);

    // Layer 2 (d=16 -> 40)
    edge_sum_d16<<<EE / 8, 128>>>(pw);
    node_gemm2<<<(NN + 7) / 8, 256>>>(W2, b2, out, pw);
}